// round 17
// baseline (speedup 1.0000x reference)
#include <cuda_runtime.h>
#include <cuda_bf16.h>
#include <cfloat>
#include <cstdint>

// ---------------------------------------------------------------------------
// RetinaNet postprocess, round 17: three kernels, multi-band mask NMS.
//   K1 prep : class-max (4 thr/row, 1 atomicMax), decode+clip, emit into 3
//             score BANDS: (C0,inf], (C1,C0], (C2,C1], each capped at T0
//   K2 rank+pair+scan (64 blocks x 256, 128 KB dyn SMEM):
//             per-band sliced comparison-rank -> nanosleep grid barrier ->
//             per-band upper-tri IoU mask rows -> last block: for each band
//             in order: cross-flag rows vs keeps-so-far (pre-removed bits),
//             stage masks into SMEM, warp0 exact greedy; early-exit at 300.
//             Publishes kept set + g_tailcut; resets counters.
//   K3 flag+final (1024-thr blocks): tail (key <= tailcut) vs snapshot kept
//             set, compact survivor records; last block: serial reference
//             greedy over survivors (normally few/none) + argmax + output.
// Exactness: band edges are clean cuts in descending (score,idx) order;
// greedy over band0++band1++band2++tail == reference greedy; pre-removed =
// suppression by monotone earlier keeps; overflow of band b => bands >= b
// all flow through the exact tail path (tailcut handles membership).
// ---------------------------------------------------------------------------

#define MAXA   262144
#define MAXDET 300
#define T0     1024
#define W0     16
#define NB     3
#define PAIRB  64
#define BLK    256
#define BLK3   1024
#define PSTTHD 0.05f
#define CUT0   0.99995f
#define CUT1   0.99990f
#define CUT2   0.99985f
#define NMSTHD 0.5f
#define DSMEM  (T0 * W0 * 8)       // 128 KB (mask stage / rank keys / pair)

typedef unsigned long long ull;

__device__ float  g_keys [MAXA];
__device__ float4 g_boxes[MAXA];
__device__ float  g_areas[MAXA];
__device__ ull    g_ckeys[NB * T0];
__device__ int    g_cidx [NB * T0];
__device__ float4 g_cbox [NB * T0];
__device__ float  g_carea[NB * T0];
__device__ ull    g_mask [NB * T0 * W0];
__device__ ull    g_skey [MAXA];
__device__ float4 g_sbox [MAXA];
__device__ float  g_sarea[MAXA];
__device__ float4 g_kbox [MAXDET];
__device__ float  g_karea[MAXDET];
__device__ int    g_keep [MAXDET];
__device__ int    g_bcnt[NB];
__device__ int    g_nsurv;
__device__ int    g_nk;
__device__ float  g_tailcut;
__device__ unsigned g_bar, g_cnt2, g_cnt3;

__device__ __forceinline__ bool sup_test(float x1, float y1, float x2, float y2, float ar,
                                         float X1, float Y1, float X2, float Y2, float AR)
{
    float xx1 = fmaxf(x1, X1);
    float yy1 = fmaxf(y1, Y1);
    float xx2 = fminf(x2, X2);
    float yy2 = fminf(y2, Y2);
    float inter = fmaxf(xx2 - xx1, 0.0f) * fmaxf(yy2 - yy1, 0.0f);
    float iou = inter / (ar + AR - inter + 1e-8f);
    return iou > NMSTHD;
}

// ===========================================================================
// K1: prep — 64 anchors / 256-thread block; banded slab emit.
// ===========================================================================
__global__ void __launch_bounds__(BLK)
prep_kernel(const float* __restrict__ cls,
            const float* __restrict__ reg,
            const float* __restrict__ anc,
            const int*   __restrict__ ph,
            const int*   __restrict__ pw,
            int A, int C)
{
    __shared__ unsigned srow[64];
    int t = threadIdx.x;
    int base = blockIdx.x * 64;
    if (t < 64) srow[t] = 0u;
    __syncthreads();

    if ((C & 3) == 0) {
        int f4r = C >> 2;
        int row  = t >> 2;
        int part = t & 3;
        if (base + row < A) {
            const float4* rp = (const float4*)cls + (size_t)(base + row) * f4r;
            float m = -FLT_MAX;
            #pragma unroll 5
            for (int j = part; j < f4r; j += 4) {
                float4 v = rp[j];
                m = fmaxf(m, fmaxf(fmaxf(v.x, v.y), fmaxf(v.z, v.w)));
            }
            atomicMax(&srow[row], __float_as_uint(m));
        }
    } else {
        for (int i = t; i < 64 * C; i += BLK) {
            int r = i / C;
            if (base + r < A) {
                float m = cls[(size_t)(base + r) * C + (i % C)];
                atomicMax(&srow[r], __float_as_uint(m));
            }
        }
    }
    __syncthreads();

    if (t < 64 && base + t < A) {
        int a = base + t;
        float m = __uint_as_float(srow[t]);
        g_keys[a] = (m > PSTTHD) ? m : 0.0f;
        if (m > CUT2) {
            int band = (m > CUT0) ? 0 : ((m > CUT1) ? 1 : 2);
            int p = atomicAdd(&g_bcnt[band], 1);
            if (p < T0)
                g_ckeys[band * T0 + p] = ((ull)__float_as_uint(m) << 18) |
                                         (ull)(0x3FFFFu - (unsigned)a);
        }
        float4 an = ((const float4*)anc)[a];
        float4 rg = ((const float4*)reg)[a];
        float bw = an.z - an.x;
        float bh = an.w - an.y;
        float cx = an.x + 0.5f * bw;
        float cy = an.y + 0.5f * bh;
        float pcx = cx + (rg.x * 0.1f) * bw;
        float pcy = cy + (rg.y * 0.1f) * bh;
        float pw_ = expf(rg.z * 0.2f) * bw;
        float ph_ = expf(rg.w * 0.2f) * bh;
        float Wd = pw ? (float)__ldg(pw) : 1024.0f;
        float Hd = ph ? (float)__ldg(ph) : 1024.0f;
        float x1 = fmaxf(pcx - 0.5f * pw_, 0.0f);
        float y1 = fmaxf(pcy - 0.5f * ph_, 0.0f);
        float x2 = fminf(pcx + 0.5f * pw_, Wd);
        float y2 = fminf(pcy + 0.5f * ph_, Hd);
        g_boxes[a] = make_float4(x1, y1, x2, y2);
        g_areas[a] = (x2 - x1) * (y2 - y1);
    }
}

// ===========================================================================
// K2: per-band rank -> barrier -> per-band pair -> last-block banded scan.
// ===========================================================================
__global__ void __launch_bounds__(BLK)
rank_pair_scan_kernel()
{
    extern __shared__ char dyn[];
    __shared__ int    sranks[32];
    __shared__ int    spos[MAXDET];
    __shared__ float4 kbx[MAXDET];
    __shared__ float  kar[MAXDET];
    __shared__ ull    sremoved[W0];
    __shared__ int    snk;
    __shared__ int    is_last;

    int t = threadIdx.x;
    int lane = t & 31;

    int bcnt[NB], nproc = 0;
    #pragma unroll
    for (int b = 0; b < NB; b++) bcnt[b] = g_bcnt[b];
    for (int b = 0; b < NB; b++) { if (bcnt[b] > T0) break; nproc++; }
    static const float cutlow_h[NB] = {CUT0, CUT1, CUT2};
    float tailcut = (nproc == 0) ? 1e30f : cutlow_h[nproc - 1];

    // ---- rank: per band, 8 threads per item, sliced over 64 blocks ----
    for (int b = 0; b < nproc; b++) {
        int n = bcnt[b];
        if (n == 0) continue;
        ull* skeys = (ull*)dyn;
        for (int i = t; i < n; i += BLK) skeys[i] = g_ckeys[b * T0 + i];
        if (t < 32) sranks[t] = 0;
        __syncthreads();

        int per = (n + PAIRB - 1) / PAIRB;        // <= 16
        int lo = blockIdx.x * per;
        int item = t >> 3;
        int sl   = t & 7;
        int i = lo + item;
        if (item < per && i < n) {
            ull mykey = skeys[i];
            int jlo = (sl * n) >> 3;
            int jhi = ((sl + 1) * n) >> 3;
            int r = 0;
            for (int j = jlo; j < jhi; j++) r += (skeys[j] > mykey) ? 1 : 0;
            atomicAdd(&sranks[item], r);
        }
        __syncthreads();
        if (sl == 0 && item < per && i < n) {
            ull mykey = skeys[i];
            int r = sranks[item];
            int a = (int)(0x3FFFFu - (unsigned)(mykey & 0x3FFFFULL));
            g_cidx[b * T0 + r]  = a;
            g_cbox[b * T0 + r]  = g_boxes[a];
            g_carea[b * T0 + r] = g_areas[a];
        }
        __syncthreads();
    }

    // ---- grid barrier over 64 co-resident blocks ----
    __threadfence();
    __syncthreads();
    if (t == 0) {
        atomicAdd(&g_bar, 1u);
        while (*((volatile unsigned*)&g_bar) < PAIRB)
            __nanosleep(128);
    }
    __syncthreads();

    // ---- pair: per band upper-triangular masks ----
    for (int b = 0; b < nproc; b++) {
        int n = bcnt[b];
        if (n == 0) continue;
        float4* scb = (float4*)dyn;
        float*  sca = (float*)(dyn + T0 * sizeof(float4));
        for (int i = t; i < n; i += BLK) {
            scb[i] = g_cbox[b * T0 + i];
            sca[i] = g_carea[b * T0 + i];
        }
        __syncthreads();
        int items = n * W0;
        for (int it = blockIdx.x * BLK + t; it < items; it += PAIRB * BLK) {
            int i = it >> 4;
            int w = it & 15;
            int jbase = w << 6;
            int jstart = max(jbase, i + 1);
            int jend   = min(jbase + 64, n);
            ull word = 0ULL;
            if (jstart < jend) {
                float4 bi = scb[i];
                float  ai = sca[i];
                for (int j = jstart; j < jend; j++) {
                    float4 bj = scb[j];
                    if (sup_test(bi.x, bi.y, bi.z, bi.w, ai,
                                 bj.x, bj.y, bj.z, bj.w, sca[j]))
                        word |= 1ULL << (j - jbase);
                }
            }
            g_mask[b * T0 * W0 + it] = word;
        }
        __syncthreads();
    }

    // ---- epilogue: last block scans bands in order ----
    __threadfence();
    __syncthreads();
    if (t == 0) {
        unsigned old = atomicAdd(&g_cnt2, 1u);
        is_last = (old == PAIRB - 1u) ? 1 : 0;
    }
    __syncthreads();
    if (!is_last) return;
    __threadfence();
    if (t == 0) snk = 0;
    __syncthreads();

    ull* smask = (ull*)dyn;
    int nk = 0;
    for (int b = 0; b < nproc && nk < MAXDET; b++) {
        int n = bcnt[b];
        if (n == 0) continue;

        // cross-band pre-removed: rows vs keeps from earlier bands
        if (t < W0) sremoved[t] = 0ULL;
        __syncthreads();
        if (nk > 0) {
            for (int i = t; i < n; i += BLK) {
                float4 bx = g_cbox[b * T0 + i];
                float  ar = g_carea[b * T0 + i];
                for (int k = 0; k < nk; k++) {
                    if (sup_test(bx.x, bx.y, bx.z, bx.w, ar,
                                 kbx[k].x, kbx[k].y, kbx[k].z, kbx[k].w, kar[k])) {
                        atomicOr(&sremoved[i >> 6], 1ULL << (i & 63));
                        break;
                    }
                }
            }
        }
        __syncthreads();

        // stage this band's masks into SMEM
        int nwords = n * W0;
        for (int i = t; i < nwords; i += BLK) smask[i] = g_mask[b * T0 * W0 + i];
        __syncthreads();

        // warp0: exact greedy over the band
        if (t < 32) {
            ull removed = (lane < W0) ? sremoved[lane] : 0ULL;
            int nkl = snk;
            int nchunks = (n + 15) >> 4;
            for (int c = 0; c < nchunks && nkl < MAXDET; c++) {
                int cb = c << 4;
                ull buf[16];
                #pragma unroll
                for (int r = 0; r < 16; r++) {
                    int i = cb + r;
                    buf[r] = (lane < W0 && i < n) ? smask[i * W0 + lane] : 0ULL;
                }
                int lim = min(16, n - cb);
                int widx = cb >> 6;
                ull dec = 0ULL;
                if (lane == widx) {
                    ull w = removed;
                    for (int r = 0; r < lim; r++) {
                        int bit = (cb + r) & 63;
                        if (!((w >> bit) & 1ULL)) {
                            dec |= 1ULL << r;
                            w |= buf[r];
                        }
                    }
                    removed = w;
                }
                dec = __shfl_sync(0xffffffffu, dec, widx);
                while (dec) {
                    int r = __ffsll(dec) - 1;
                    dec &= dec - 1;
                    removed |= buf[r];
                    if (lane == 0) spos[nkl] = b * T0 + cb + r;
                    nkl++;
                    if (nkl >= MAXDET) break;
                }
            }
            if (lane == 0) snk = nkl;
        }
        __syncthreads();

        // resolve new keeps into kept SMEM + globals
        int newnk = snk;
        for (int k = nk + t; k < newnk; k += BLK) {
            int gp = spos[k];
            float4 bx = g_cbox[gp];
            float  ar = g_carea[gp];
            g_keep[k]  = g_cidx[gp];
            g_kbox[k]  = bx;
            g_karea[k] = ar;
            kbx[k] = bx;
            kar[k] = ar;
        }
        __syncthreads();
        nk = newnk;
    }

    if (t == 0) {
        g_nk = nk;
        g_tailcut = tailcut;
        #pragma unroll
        for (int b = 0; b < NB; b++) g_bcnt[b] = 0;   // next replay clean
        g_nsurv = 0;
        g_cnt2 = 0;
        g_bar = 0;
    }
}

// ===========================================================================
// K3: flag (grid, 1024-thr, compact survivor records) + last block:
// serial reference greedy over survivors + final output.
// ===========================================================================
__global__ void __launch_bounds__(BLK3)
flag_final_kernel(const float* __restrict__ cls, int A, int C,
                  float* __restrict__ out)
{
    __shared__ float4 skb[MAXDET];
    __shared__ float  ska[MAXDET];
    __shared__ ull    sb[BLK3];
    __shared__ float4 swin;
    __shared__ float  swar;
    __shared__ int    is_last;
    int t = threadIdx.x;
    int lane = t & 31;
    int wrp = t >> 5;

    // ---- flag: tail (key <= tailcut) vs snapshot kept set ----
    int nk = g_nk;
    if (nk < MAXDET) {
        float tailcut = g_tailcut;
        for (int k = t; k < nk; k += BLK3) {
            skb[k] = g_kbox[k];
            ska[k] = g_karea[k];
        }
        __syncthreads();
        int a = blockIdx.x * BLK3 + t;
        if (a < A) {
            float key = g_keys[a];
            if (key > PSTTHD && !(key > tailcut)) {
                float4 b = g_boxes[a];
                float ar = g_areas[a];
                bool sup = false;
                for (int k = 0; k < nk; k++) {
                    if (sup_test(b.x, b.y, b.z, b.w, ar,
                                 skb[k].x, skb[k].y, skb[k].z, skb[k].w, ska[k])) {
                        sup = true;
                        break;
                    }
                }
                if (!sup) {
                    int p = atomicAdd(&g_nsurv, 1);
                    g_skey [p] = ((ull)__float_as_uint(key) << 18) |
                                 (ull)(0x3FFFFu - (unsigned)a);
                    g_sbox [p] = b;
                    g_sarea[p] = ar;
                }
            }
        }
    }

    // ---- epilogue selection ----
    __threadfence();
    __syncthreads();
    if (t == 0) {
        unsigned old = atomicAdd(&g_cnt3, 1u);
        is_last = (old == gridDim.x - 1u) ? 1 : 0;
    }
    __syncthreads();
    if (!is_last) return;
    __threadfence();

    // ---- serial reference greedy over compact survivors ----
    int nk3 = g_nk;
    int ns = g_nsurv;
    while (nk3 < MAXDET && ns > 0) {
        ull best = 0ULL;
        for (int i = t; i < ns; i += BLK3) {
            ull v = g_skey[i];
            if (v > best) best = v;
        }
        sb[t] = best;
        __syncthreads();
        for (int off = BLK3 / 2; off; off >>= 1) {
            if (t < off && sb[t + off] > sb[t]) sb[t] = sb[t + off];
            __syncthreads();
        }
        if (sb[0] == 0ULL) break;

        if (t == 0) {
            int a = (int)(0x3FFFFu - (unsigned)(sb[0] & 0x3FFFFULL));
            float4 b = g_boxes[a];
            float ar = g_areas[a];
            g_keep[nk3]  = a;
            g_kbox[nk3]  = b;
            g_karea[nk3] = ar;
            swin = b;
            swar = ar;
        }
        __syncthreads();
        float4 wb = swin;
        float war = swar;
        for (int i = t; i < ns; i += BLK3) {
            ull v = g_skey[i];
            if (v != 0ULL) {
                float4 b = g_sbox[i];
                if (sup_test(b.x, b.y, b.z, b.w, g_sarea[i],
                             wb.x, wb.y, wb.z, wb.w, war))
                    g_skey[i] = 0ULL;      // winner self-suppresses too
            }
        }
        nk3++;
        __syncthreads();
    }
    __syncthreads();

    // ---- final output: 32 warps cover 300 keeps ----
    for (int d = wrp; d < MAXDET; d += BLK3 / 32) {
        bool valid = d < nk3;
        float score = 0.f, clsid = -1.f;
        float bx0 = 0.f, bx1 = 0.f, bx2 = 0.f, bx3 = 0.f;
        if (valid) {
            int idx = g_keep[d];
            const float* row = cls + (size_t)idx * C;
            float best = -FLT_MAX;
            int bi = 0x7fffffff;
            for (int c = lane; c < C; c += 32) {
                float vv = row[c];
                if (vv > best) { best = vv; bi = c; }
            }
            #pragma unroll
            for (int off = 16; off; off >>= 1) {
                float ov = __shfl_down_sync(0xffffffffu, best, off);
                int   oi = __shfl_down_sync(0xffffffffu, bi,   off);
                if (ov > best || (ov == best && oi < bi)) { best = ov; bi = oi; }
            }
            best = __shfl_sync(0xffffffffu, best, 0);
            bi   = __shfl_sync(0xffffffffu, bi,   0);
            score = best;
            clsid = (float)bi;
            float4 b = g_kbox[d];
            bx0 = b.x; bx1 = b.y; bx2 = b.z; bx3 = b.w;
        }
        if (lane == 0) {
            out[d]                      = score;
            out[MAXDET + d]             = clsid;
            out[2 * MAXDET + 4 * d + 0] = bx0;
            out[2 * MAXDET + 4 * d + 1] = bx1;
            out[2 * MAXDET + 4 * d + 2] = bx2;
            out[2 * MAXDET + 4 * d + 3] = bx3;
            out[6 * MAXDET + d]         = valid ? 1.0f : 0.0f;
        }
    }
    __syncthreads();
    if (t == 0) g_cnt3 = 0;
}

// ---------------------------------------------------------------------------
extern "C" void kernel_launch(void* const* d_in, const int* in_sizes, int n_in,
                              void* d_out, int out_size)
{
    const float* cls = (const float*)d_in[0];
    const float* reg = (const float*)d_in[1];
    const float* anc = (const float*)d_in[2];
    const int*   ph  = (n_in > 3) ? (const int*)d_in[3] : nullptr;
    const int*   pw  = (n_in > 4) ? (const int*)d_in[4] : nullptr;

    int A = in_sizes[2] / 4;
    if (A > MAXA) A = MAXA;
    int C = in_sizes[0] / A;

    static int configured = 0;
    if (!configured) {
        cudaFuncSetAttribute(rank_pair_scan_kernel,
                             cudaFuncAttributeMaxDynamicSharedMemorySize, DSMEM);
        configured = 1;
    }

    prep_kernel<<<(A + 63) / 64, BLK>>>(cls, reg, anc, ph, pw, A, C);
    rank_pair_scan_kernel<<<PAIRB, BLK, DSMEM>>>();
    flag_final_kernel<<<(A + BLK3 - 1) / BLK3, BLK3>>>(cls, A, C, (float*)d_out);
}